// round 1
// baseline (speedup 1.0000x reference)
#include <cuda_runtime.h>
#include <math.h>

// ---------------- problem constants ----------------
#define BB      2
#define CC0     48          // dim
#define NHEADS  2
#define CHD     24          // channels per head
#define NTOK    4096        // 64*64
#define C3      144         // dim*3
#define HID     96
#define HID2    192
#define NWARPS  8

// ---------------- scratch (device globals; no allocation allowed) ----------
__device__ float g_qkv1[BB*C3*NTOK];
__device__ float g_qkv2[BB*C3*NTOK];
__device__ float g_q [BB*NHEADS*NTOK*CHD];
__device__ float g_k [BB*NHEADS*NTOK*CHD];
__device__ float g_v [BB*NHEADS*NTOK*CHD];
__device__ float g_o [BB*NHEADS*NTOK*CHD];
__device__ float g_x1[BB*CC0*NTOK];
__device__ float g_ff1[BB*HID2*NTOK];
__device__ float g_ff2[BB*HID2*NTOK];

// ---------------- packed f32x2 helpers (FFMA2: PTX-only, 2x fp32 rate) ----
__device__ __forceinline__ unsigned long long pack2(float lo, float hi) {
    unsigned long long r;
    asm("mov.b64 %0, {%1, %2};" : "=l"(r) : "f"(lo), "f"(hi));
    return r;
}
__device__ __forceinline__ void unpack2(unsigned long long v, float& lo, float& hi) {
    asm("mov.b64 {%0, %1}, %2;" : "=f"(lo), "=f"(hi) : "l"(v));
}
__device__ __forceinline__ unsigned long long ffma2(unsigned long long a,
                                                    unsigned long long b,
                                                    unsigned long long c) {
    unsigned long long d;
    asm("fma.rn.f32x2 %0, %1, %2, %3;" : "=l"(d) : "l"(a), "l"(b), "l"(c));
    return d;
}

// ---------------- LayerNorm (over channels) + 1x1 conv, warp per pixel -----
template<int CIN, int COUT>
__global__ void __launch_bounds__(32*NWARPS)
ln_conv1x1_kernel(const float* __restrict__ x,
                  const float* __restrict__ lnw, const float* __restrict__ lnb,
                  const float* __restrict__ cw,  const float* __restrict__ cb,
                  float* __restrict__ out)
{
    __shared__ float Wt[CIN*COUT];        // transposed [c][o]
    __shared__ float xs[NWARPS][CIN];
    for (int i = threadIdx.x; i < CIN*COUT; i += blockDim.x) {
        int o = i % COUT, c = i / COUT;
        Wt[i] = cw[o*CIN + c];
    }
    __syncthreads();
    int warp = threadIdx.x >> 5, lane = threadIdx.x & 31;
    int pix  = blockIdx.x * NWARPS + warp;      // [0, BB*NTOK)
    int b = pix / NTOK, n = pix % NTOK;
    const float* xp = x + b*CIN*NTOK + n;
    float v0 = (lane      < CIN) ? xp[lane*NTOK]      : 0.f;
    float v1 = (lane + 32 < CIN) ? xp[(lane+32)*NTOK] : 0.f;
    float s = v0 + v1, ss = v0*v0 + v1*v1;
    #pragma unroll
    for (int off = 16; off; off >>= 1) {
        s  += __shfl_xor_sync(0xffffffffu, s,  off);
        ss += __shfl_xor_sync(0xffffffffu, ss, off);
    }
    float mu  = s  * (1.f/CIN);
    float var = ss * (1.f/CIN) - mu*mu;
    float inv = rsqrtf(var + 1e-5f);
    if (lane      < CIN) xs[warp][lane]    = (v0 - mu)*inv*lnw[lane]    + lnb[lane];
    if (lane + 32 < CIN) xs[warp][lane+32] = (v1 - mu)*inv*lnw[lane+32] + lnb[lane+32];
    __syncwarp();
    for (int o = lane; o < COUT; o += 32) {
        float acc = cb[o];
        #pragma unroll
        for (int c = 0; c < CIN; c++) acc += Wt[c*COUT + o] * xs[warp][c];
        out[b*COUT*NTOK + o*NTOK + n] = acc;
    }
}

// ---------------- depthwise 3x3, SAME (zero pad) ---------------------------
template<int CCH>
__global__ void dwconv3_kernel(const float* __restrict__ in, const float* __restrict__ w,
                               const float* __restrict__ bias, float* __restrict__ out)
{
    int idx = blockIdx.x*blockDim.x + threadIdx.x;   // over BB*CCH*NTOK
    if (idx >= BB*CCH*NTOK) return;
    int p  = idx & (NTOK-1);
    int bc = idx >> 12;
    int c  = bc % CCH;
    int x0 = p & 63, y0 = p >> 6;
    const float* ip = in + bc*NTOK;
    const float* wp = w + c*9;
    float acc = bias[c];
    #pragma unroll
    for (int ky = 0; ky < 3; ky++) {
        int y = y0 + ky - 1;
        if ((unsigned)y < 64u) {
            #pragma unroll
            for (int kx = 0; kx < 3; kx++) {
                int xx = x0 + kx - 1;
                if ((unsigned)xx < 64u) acc += wp[ky*3 + kx] * ip[y*64 + xx];
            }
        }
    }
    out[idx] = acc;
}

// ---------------- split q/k/v, l2-normalize, fold temperature into q -------
// output layout: [bh][n][24] (token-major, contiguous head dim)
__global__ void qkv_norm_kernel(const float* __restrict__ qkv, const float* __restrict__ temp,
                                float* __restrict__ Q, float* __restrict__ K,
                                float* __restrict__ V)
{
    int idx = blockIdx.x*blockDim.x + threadIdx.x;   // over BB*NHEADS*NTOK
    if (idx >= BB*NHEADS*NTOK) return;
    int n  = idx & (NTOK-1);
    int bh = idx >> 12;
    int b = bh >> 1, hd = bh & 1;
    const float* base = qkv + b*C3*NTOK + n;
    float t = temp[hd];
    float buf[CHD];
    // q: channels hd*24 .. +23
    float ss = 0.f;
    #pragma unroll
    for (int c = 0; c < CHD; c++) { float u = base[(hd*CHD + c)*NTOK]; buf[c] = u; ss += u*u; }
    float inv = t / fmaxf(sqrtf(ss), 1e-12f);
    float* Qp = Q + idx*CHD;
    #pragma unroll
    for (int c = 0; c < CHD; c++) Qp[c] = buf[c]*inv;
    // k: channels 48 + hd*24 ..
    ss = 0.f;
    #pragma unroll
    for (int c = 0; c < CHD; c++) { float u = base[(CC0 + hd*CHD + c)*NTOK]; buf[c] = u; ss += u*u; }
    inv = 1.f / fmaxf(sqrtf(ss), 1e-12f);
    float* Kp = K + idx*CHD;
    #pragma unroll
    for (int c = 0; c < CHD; c++) Kp[c] = buf[c]*inv;
    // v: channels 96 + hd*24 ..
    float* Vp = V + idx*CHD;
    #pragma unroll
    for (int c = 0; c < CHD; c++) Vp[c] = base[(2*CC0 + hd*CHD + c)*NTOK];
}

// ---------------- flash attention, fixed softmax shift m = |temp| ----------
// logits = temp*(q_hat . k_hat) in [-|t|, |t|]  ==>  exp(s - |t|) never
// overflows and no running max is needed; split-K partials merge by summation.
#define BQ     64
#define NSPLIT 4
#define BK     64
#define KVSEG  (NTOK/NSPLIT)   // 1024

__global__ void __launch_bounds__(256)
attn_kernel(const float* __restrict__ Q, const float* __restrict__ K,
            const float* __restrict__ V, const float* __restrict__ temp,
            float* __restrict__ O)
{
    __shared__ float smem[2*NSPLIT*BK*CHD];      // 12288 floats = 48KB
    float* sK = smem;
    float* sV = smem + NSPLIT*BK*CHD;
    int tid   = threadIdx.x;
    int split = tid >> 6;        // 0..3
    int qr    = tid & 63;        // query row within tile
    int bh    = blockIdx.y;
    int hd    = bh & 1;
    int q0    = blockIdx.x * BQ;

    float m = fabsf(temp[hd]);

    const float* qp = Q + (size_t)(bh*NTOK + q0 + qr)*CHD;
    unsigned long long q2[12];
    #pragma unroll
    for (int i = 0; i < 6; i++) {
        float4 t4 = ((const float4*)qp)[i];
        q2[2*i]   = pack2(t4.x, t4.y);
        q2[2*i+1] = pack2(t4.z, t4.w);
    }
    unsigned long long o2[12];
    #pragma unroll
    for (int i = 0; i < 12; i++) o2[i] = 0ULL;
    float l = 0.f;

    int kv0 = split * KVSEG;
    const float4* kg  = (const float4*)(K + (size_t)(bh*NTOK + kv0)*CHD);
    const float4* vg  = (const float4*)(V + (size_t)(bh*NTOK + kv0)*CHD);
    float4* sk4 = (float4*)(sK + split*BK*CHD);
    float4* sv4 = (float4*)(sV + split*BK*CHD);
    const unsigned long long* k8 = (const unsigned long long*)(sK + split*BK*CHD);
    const unsigned long long* v8 = (const unsigned long long*)(sV + split*BK*CHD);

    for (int kb = 0; kb < KVSEG; kb += BK) {
        __syncthreads();
        int base4 = kb * (CHD/4);
        #pragma unroll
        for (int i = 0; i < (BK*CHD/4)/64; i++) {   // 6 iters
            int j = qr + i*64;
            sk4[j] = kg[base4 + j];
            sv4[j] = vg[base4 + j];
        }
        __syncthreads();
        #pragma unroll 2
        for (int kk = 0; kk < BK; kk++) {
            const unsigned long long* kr = k8 + kk*12;
            unsigned long long sa = 0ULL, sb = 0ULL;
            #pragma unroll
            for (int i = 0; i < 12; i += 2) {
                sa = ffma2(q2[i],   kr[i],   sa);
                sb = ffma2(q2[i+1], kr[i+1], sb);
            }
            float xlo, xhi, ylo, yhi;
            unpack2(sa, xlo, xhi); unpack2(sb, ylo, yhi);
            float s = (xlo + xhi) + (ylo + yhi);
            float p = __expf(s - m);
            l += p;
            unsigned long long p2 = pack2(p, p);
            const unsigned long long* vr = v8 + kk*12;
            #pragma unroll
            for (int i = 0; i < 12; i++) o2[i] = ffma2(p2, vr[i], o2[i]);
        }
    }

    // merge the 4 split-K partials (same shift m => plain sum)
    __syncthreads();
    float* part = smem;                      // [qr][split][25] : l, o[24]
    float* mine = part + (qr*NSPLIT + split)*25;
    mine[0] = l;
    #pragma unroll
    for (int i = 0; i < 12; i++) {
        float lo, hi; unpack2(o2[i], lo, hi);
        mine[1 + 2*i] = lo; mine[2 + 2*i] = hi;
    }
    __syncthreads();
    if (tid < 64) {
        float L = 0.f;
        float oo[CHD];
        #pragma unroll
        for (int c = 0; c < CHD; c++) oo[c] = 0.f;
        #pragma unroll
        for (int sp = 0; sp < NSPLIT; sp++) {
            const float* pp = part + (tid*NSPLIT + sp)*25;
            L += pp[0];
            #pragma unroll
            for (int c = 0; c < CHD; c++) oo[c] += pp[1 + c];
        }
        float invL = 1.f / L;
        float* op = O + (size_t)(bh*NTOK + q0 + tid)*CHD;
        #pragma unroll
        for (int c = 0; c < CHD; c++) op[c] = oo[c]*invL;
    }
}

// ---------------- proj 1x1 + residual, warp per pixel ----------------------
__global__ void __launch_bounds__(32*NWARPS)
proj_res_kernel(const float* __restrict__ x, const float* __restrict__ Ot,
                const float* __restrict__ pw, const float* __restrict__ pb,
                float* __restrict__ out)
{
    __shared__ float Wt[CC0*CC0];
    __shared__ float xs[NWARPS][CC0];
    for (int i = threadIdx.x; i < CC0*CC0; i += blockDim.x) {
        int o = i % CC0, c = i / CC0;
        Wt[i] = pw[o*CC0 + c];
    }
    __syncthreads();
    int warp = threadIdx.x >> 5, lane = threadIdx.x & 31;
    int pix  = blockIdx.x * NWARPS + warp;
    int b = pix / NTOK, n = pix % NTOK;
    if (lane < CHD) {
        xs[warp][lane]       = Ot[((size_t)(b*NHEADS + 0)*NTOK + n)*CHD + lane];
        xs[warp][CHD + lane] = Ot[((size_t)(b*NHEADS + 1)*NTOK + n)*CHD + lane];
    }
    __syncwarp();
    for (int o = lane; o < CC0; o += 32) {
        float acc = pb[o];
        #pragma unroll
        for (int c = 0; c < CC0; c++) acc += Wt[c*CC0 + o] * xs[warp][c];
        int gi = b*CC0*NTOK + o*NTOK + n;
        out[gi] = x[gi] + acc;
    }
}

// ---------------- gelu-gate + fo 1x1 + residual, warp per pixel ------------
__global__ void __launch_bounds__(32*NWARPS)
ffn_out_kernel(const float* __restrict__ x1, const float* __restrict__ y,
               const float* __restrict__ fow, const float* __restrict__ fob,
               float* __restrict__ out)
{
    __shared__ float Wt[HID*CC0];    // [j][o]
    __shared__ float gs[NWARPS][HID];
    for (int i = threadIdx.x; i < HID*CC0; i += blockDim.x) {
        int o = i % CC0, j = i / CC0;
        Wt[i] = fow[o*HID + j];
    }
    __syncthreads();
    int warp = threadIdx.x >> 5, lane = threadIdx.x & 31;
    int pix  = blockIdx.x * NWARPS + warp;
    int b = pix / NTOK, n = pix % NTOK;
    const float* yp = y + b*HID2*NTOK + n;
    #pragma unroll
    for (int j = lane; j < HID; j += 32) {
        float a  = yp[j*NTOK];
        float g2 = yp[(HID + j)*NTOK];
        float g  = 0.5f*a*(1.f + erff(a*0.70710678118654752f));   // exact gelu
        gs[warp][j] = g*g2;
    }
    __syncwarp();
    for (int o = lane; o < CC0; o += 32) {
        float acc = fob[o];
        #pragma unroll
        for (int j = 0; j < HID; j++) acc += Wt[j*CC0 + o] * gs[warp][j];
        int gi = b*CC0*NTOK + o*NTOK + n;
        out[gi] = x1[gi] + acc;
    }
}

// ---------------- launch ----------------------------------------------------
extern "C" void kernel_launch(void* const* d_in, const int* in_sizes, int n_in,
                              void* d_out, int out_size)
{
    const float* x    = (const float*)d_in[0];
    const float* n1w  = (const float*)d_in[1];
    const float* n1b  = (const float*)d_in[2];
    const float* qkvw = (const float*)d_in[3];
    const float* qkvb = (const float*)d_in[4];
    const float* qdww = (const float*)d_in[5];
    const float* qdwb = (const float*)d_in[6];
    const float* temp = (const float*)d_in[7];
    const float* pw   = (const float*)d_in[8];
    const float* pb   = (const float*)d_in[9];
    const float* n2w  = (const float*)d_in[10];
    const float* n2b  = (const float*)d_in[11];
    const float* fiw  = (const float*)d_in[12];
    const float* fib  = (const float*)d_in[13];
    const float* fdww = (const float*)d_in[14];
    const float* fdwb = (const float*)d_in[15];
    const float* fow  = (const float*)d_in[16];
    const float* fob  = (const float*)d_in[17];
    float* out = (float*)d_out;

    float *qkv1, *qkv2, *Qp, *Kp, *Vp, *Op, *x1, *ff1, *ff2;
    cudaGetSymbolAddress((void**)&qkv1, g_qkv1);
    cudaGetSymbolAddress((void**)&qkv2, g_qkv2);
    cudaGetSymbolAddress((void**)&Qp,   g_q);
    cudaGetSymbolAddress((void**)&Kp,   g_k);
    cudaGetSymbolAddress((void**)&Vp,   g_v);
    cudaGetSymbolAddress((void**)&Op,   g_o);
    cudaGetSymbolAddress((void**)&x1,   g_x1);
    cudaGetSymbolAddress((void**)&ff1,  g_ff1);
    cudaGetSymbolAddress((void**)&ff2,  g_ff2);

    const int pixblocks = (BB*NTOK) / NWARPS;   // 1024

    ln_conv1x1_kernel<CC0, C3><<<pixblocks, 32*NWARPS>>>(x, n1w, n1b, qkvw, qkvb, qkv1);
    dwconv3_kernel<C3><<<(BB*C3*NTOK + 255)/256, 256>>>(qkv1, qdww, qdwb, qkv2);
    qkv_norm_kernel<<<(BB*NHEADS*NTOK + 255)/256, 256>>>(qkv2, temp, Qp, Kp, Vp);

    dim3 ag(NTOK/BQ, BB*NHEADS);                // (64, 4)
    attn_kernel<<<ag, 256>>>(Qp, Kp, Vp, temp, Op);

    proj_res_kernel<<<pixblocks, 32*NWARPS>>>(x, Op, pw, pb, x1);
    ln_conv1x1_kernel<CC0, HID2><<<pixblocks, 32*NWARPS>>>(x1, n2w, n2b, fiw, fib, ff1);
    dwconv3_kernel<HID2><<<(BB*HID2*NTOK + 255)/256, 256>>>(ff1, fdww, fdwb, ff2);
    ffn_out_kernel<<<pixblocks, 32*NWARPS>>>(x1, ff2, fow, fob, out);
}

// round 2
// speedup vs baseline: 2.0766x; 2.0766x over previous
#include <cuda_runtime.h>
#include <cuda_bf16.h>
#include <math.h>

// ---------------- problem constants ----------------
#define BB      2
#define CC0     48          // dim
#define NHEADS  2
#define CHD     24          // channels per head
#define DP      32          // padded head dim (bf16 tensors)
#define NTOK    4096        // 64*64
#define C3      144         // dim*3
#define HID     96
#define HID2    192
#define NWARPS  8

// ---------------- scratch (device globals; no allocation allowed) ----------
__device__ float g_qkv1[BB*C3*NTOK];
__device__ float g_qkv2[BB*C3*NTOK];
__device__ __nv_bfloat16 g_qb[BB*NHEADS*NTOK*DP];
__device__ __nv_bfloat16 g_kb[BB*NHEADS*NTOK*DP];
__device__ __nv_bfloat16 g_vb[BB*NHEADS*NTOK*DP];
__device__ float g_o [BB*NHEADS*NTOK*CHD];
__device__ float g_x1[BB*CC0*NTOK];
__device__ float g_ff1[BB*HID2*NTOK];
__device__ float g_ff2[BB*HID2*NTOK];

// ---------------- small asm helpers ----------------------------------------
__device__ __forceinline__ unsigned smem_u32(const void* p) {
    return (unsigned)__cvta_generic_to_shared(p);
}
__device__ __forceinline__ void ldmx4(unsigned& r0, unsigned& r1, unsigned& r2,
                                      unsigned& r3, unsigned a) {
    asm volatile("ldmatrix.sync.aligned.m8n8.x4.shared.b16 {%0,%1,%2,%3}, [%4];"
                 : "=r"(r0), "=r"(r1), "=r"(r2), "=r"(r3) : "r"(a));
}
__device__ __forceinline__ void ldmx4t(unsigned& r0, unsigned& r1, unsigned& r2,
                                       unsigned& r3, unsigned a) {
    asm volatile("ldmatrix.sync.aligned.m8n8.x4.trans.shared.b16 {%0,%1,%2,%3}, [%4];"
                 : "=r"(r0), "=r"(r1), "=r"(r2), "=r"(r3) : "r"(a));
}
__device__ __forceinline__ void mma16816(float& d0, float& d1, float& d2, float& d3,
                                         unsigned a0, unsigned a1, unsigned a2, unsigned a3,
                                         unsigned b0, unsigned b1) {
    asm volatile("mma.sync.aligned.m16n8k16.row.col.f32.bf16.bf16.f32 "
                 "{%0,%1,%2,%3},{%4,%5,%6,%7},{%8,%9},{%0,%1,%2,%3};"
                 : "+f"(d0), "+f"(d1), "+f"(d2), "+f"(d3)
                 : "r"(a0), "r"(a1), "r"(a2), "r"(a3), "r"(b0), "r"(b1));
}
// pack {lo,hi} floats into bf16x2 (first src -> high half per PTX)
__device__ __forceinline__ unsigned cvt2(float hi, float lo) {
    unsigned r;
    asm("cvt.rn.bf16x2.f32 %0, %1, %2;" : "=r"(r) : "f"(hi), "f"(lo));
    return r;
}
__device__ __forceinline__ float ex2f(float x) {
    float y; asm("ex2.approx.ftz.f32 %0, %1;" : "=f"(y) : "f"(x)); return y;
}

// ---------------- LayerNorm (over channels) + 1x1 conv, warp per pixel -----
template<int CIN, int COUT>
__global__ void __launch_bounds__(32*NWARPS)
ln_conv1x1_kernel(const float* __restrict__ x,
                  const float* __restrict__ lnw, const float* __restrict__ lnb,
                  const float* __restrict__ cw,  const float* __restrict__ cb,
                  float* __restrict__ out)
{
    __shared__ float Wt[CIN*COUT];        // transposed [c][o]
    __shared__ float xs[NWARPS][CIN];
    for (int i = threadIdx.x; i < CIN*COUT; i += blockDim.x) {
        int o = i % COUT, c = i / COUT;
        Wt[i] = cw[o*CIN + c];
    }
    __syncthreads();
    int warp = threadIdx.x >> 5, lane = threadIdx.x & 31;
    int pix  = blockIdx.x * NWARPS + warp;      // [0, BB*NTOK)
    int b = pix / NTOK, n = pix % NTOK;
    const float* xp = x + b*CIN*NTOK + n;
    float v0 = (lane      < CIN) ? xp[lane*NTOK]      : 0.f;
    float v1 = (lane + 32 < CIN) ? xp[(lane+32)*NTOK] : 0.f;
    float s = v0 + v1, ss = v0*v0 + v1*v1;
    #pragma unroll
    for (int off = 16; off; off >>= 1) {
        s  += __shfl_xor_sync(0xffffffffu, s,  off);
        ss += __shfl_xor_sync(0xffffffffu, ss, off);
    }
    float mu  = s  * (1.f/CIN);
    float var = ss * (1.f/CIN) - mu*mu;
    float inv = rsqrtf(var + 1e-5f);
    if (lane      < CIN) xs[warp][lane]    = (v0 - mu)*inv*lnw[lane]    + lnb[lane];
    if (lane + 32 < CIN) xs[warp][lane+32] = (v1 - mu)*inv*lnw[lane+32] + lnb[lane+32];
    __syncwarp();
    for (int o = lane; o < COUT; o += 32) {
        float acc = cb[o];
        #pragma unroll
        for (int c = 0; c < CIN; c++) acc += Wt[c*COUT + o] * xs[warp][c];
        out[b*COUT*NTOK + o*NTOK + n] = acc;
    }
}

// ---------------- depthwise 3x3, SAME (zero pad) ---------------------------
template<int CCH>
__global__ void dwconv3_kernel(const float* __restrict__ in, const float* __restrict__ w,
                               const float* __restrict__ bias, float* __restrict__ out)
{
    int idx = blockIdx.x*blockDim.x + threadIdx.x;   // over BB*CCH*NTOK
    if (idx >= BB*CCH*NTOK) return;
    int p  = idx & (NTOK-1);
    int bc = idx >> 12;
    int c  = bc % CCH;
    int x0 = p & 63, y0 = p >> 6;
    const float* ip = in + bc*NTOK;
    const float* wp = w + c*9;
    float acc = bias[c];
    #pragma unroll
    for (int ky = 0; ky < 3; ky++) {
        int y = y0 + ky - 1;
        if ((unsigned)y < 64u) {
            #pragma unroll
            for (int kx = 0; kx < 3; kx++) {
                int xx = x0 + kx - 1;
                if ((unsigned)xx < 64u) acc += wp[ky*3 + kx] * ip[y*64 + xx];
            }
        }
    }
    out[idx] = acc;
}

// ---------------- split q/k/v, l2-normalize, fold temp, emit bf16 ----------
// output layout: [bh][n][32] bf16 (cols 24..31 zero)
__global__ void qkv_norm_bf16_kernel(const float* __restrict__ qkv,
                                     const float* __restrict__ temp,
                                     __nv_bfloat16* __restrict__ Q,
                                     __nv_bfloat16* __restrict__ K,
                                     __nv_bfloat16* __restrict__ V)
{
    int idx = blockIdx.x*blockDim.x + threadIdx.x;   // over BB*NHEADS*NTOK
    if (idx >= BB*NHEADS*NTOK) return;
    int n  = idx & (NTOK-1);
    int bh = idx >> 12;
    int b = bh >> 1, hd = bh & 1;
    const float* base = qkv + b*C3*NTOK + n;
    float t = temp[hd];
    float buf[CHD];
    unsigned tmp[DP/2];
    #pragma unroll
    for (int i = CHD/2; i < DP/2; i++) tmp[i] = 0u;

    // q: channels hd*24 .. +23, scaled by t/||q||
    float ss = 0.f;
    #pragma unroll
    for (int c = 0; c < CHD; c++) { float u = base[(hd*CHD + c)*NTOK]; buf[c] = u; ss += u*u; }
    float inv = t / fmaxf(sqrtf(ss), 1e-12f);
    #pragma unroll
    for (int i = 0; i < CHD/2; i++) tmp[i] = cvt2(buf[2*i+1]*inv, buf[2*i]*inv);
    {
        uint4* p4 = (uint4*)(Q + (size_t)idx*DP);
        p4[0] = make_uint4(tmp[0], tmp[1], tmp[2],  tmp[3]);
        p4[1] = make_uint4(tmp[4], tmp[5], tmp[6],  tmp[7]);
        p4[2] = make_uint4(tmp[8], tmp[9], tmp[10], tmp[11]);
        p4[3] = make_uint4(tmp[12],tmp[13],tmp[14], tmp[15]);
    }
    // k: channels 48 + hd*24 .., scaled by 1/||k||
    ss = 0.f;
    #pragma unroll
    for (int c = 0; c < CHD; c++) { float u = base[(CC0 + hd*CHD + c)*NTOK]; buf[c] = u; ss += u*u; }
    inv = 1.f / fmaxf(sqrtf(ss), 1e-12f);
    #pragma unroll
    for (int i = 0; i < CHD/2; i++) tmp[i] = cvt2(buf[2*i+1]*inv, buf[2*i]*inv);
    {
        uint4* p4 = (uint4*)(K + (size_t)idx*DP);
        p4[0] = make_uint4(tmp[0], tmp[1], tmp[2],  tmp[3]);
        p4[1] = make_uint4(tmp[4], tmp[5], tmp[6],  tmp[7]);
        p4[2] = make_uint4(tmp[8], tmp[9], tmp[10], tmp[11]);
        p4[3] = make_uint4(tmp[12],tmp[13],tmp[14], tmp[15]);
    }
    // v: channels 96 + hd*24 ..
    #pragma unroll
    for (int i = 0; i < CHD/2; i++) {
        float u0 = base[(2*CC0 + hd*CHD + 2*i)*NTOK];
        float u1 = base[(2*CC0 + hd*CHD + 2*i + 1)*NTOK];
        tmp[i] = cvt2(u1, u0);
    }
    {
        uint4* p4 = (uint4*)(V + (size_t)idx*DP);
        p4[0] = make_uint4(tmp[0], tmp[1], tmp[2],  tmp[3]);
        p4[1] = make_uint4(tmp[4], tmp[5], tmp[6],  tmp[7]);
        p4[2] = make_uint4(tmp[8], tmp[9], tmp[10], tmp[11]);
        p4[3] = make_uint4(tmp[12],tmp[13],tmp[14], tmp[15]);
    }
}

// ---------------- bf16 mma.sync flash attention -----------------------------
// grid (32 q-tiles, 4 bh), 256 threads = 8 warps, warp owns 16 q rows.
// Fixed softmax shift m = |temp| (logits in [-|t|,|t|]).
__global__ void __launch_bounds__(256)
attn_mma_kernel(const __nv_bfloat16* __restrict__ Qb,
                const __nv_bfloat16* __restrict__ Kb,
                const __nv_bfloat16* __restrict__ Vb,
                const float* __restrict__ temp,
                float* __restrict__ O)
{
    // double-buffered: buf b : K tile at b*16384, V tile at b*16384+8192
    // rows padded to 128B; 16B chunk c of row r stored at slot (c ^ (r&7))
    __shared__ __align__(16) unsigned char smem_raw[2*16384];

    int tid  = threadIdx.x;
    int warp = tid >> 5, lane = tid & 31;
    int g    = lane >> 2;     // row within 8
    int t4   = lane & 3;      // col-pair selector
    int bh   = blockIdx.y;
    int q0   = blockIdx.x * 128;

    const float L2E = 1.4426950408889634f;
    float m  = fabsf(temp[bh & 1]);
    float nm = -m * L2E;

    // ---- Q fragments straight from global (A-operand layout) ----
    unsigned qf[8];
    {
        const unsigned* q32 = (const unsigned*)(Qb + (size_t)(bh*NTOK + q0 + warp*16)*DP);
        // row stride in u32 = 16
        #pragma unroll
        for (int kt = 0; kt < 2; kt++) {
            qf[kt*4+0] = q32[g*16       + kt*8 + t4];
            qf[kt*4+1] = q32[(g+8)*16   + kt*8 + t4];
            qf[kt*4+2] = q32[g*16       + kt*8 + 4 + t4];
            qf[kt*4+3] = q32[(g+8)*16   + kt*8 + 4 + t4];
        }
    }

    float o[12];
    #pragma unroll
    for (int i = 0; i < 12; i++) o[i] = 0.f;
    float l0 = 0.f, l1 = 0.f;

    const uint4* kg = (const uint4*)(Kb + (size_t)bh*NTOK*DP);
    const uint4* vg = (const uint4*)(Vb + (size_t)bh*NTOK*DP);
    int row = tid >> 2, chk = tid & 3;
    unsigned swz = row*128 + ((chk ^ (row & 7))*16);

    uint4 kreg = kg[row*4 + chk];
    uint4 vreg = vg[row*4 + chk];
    int it = 0;

    for (int kb = 0; kb < NTOK; kb += 64) {
        unsigned char* bufK = smem_raw + it*16384;
        unsigned char* bufV = bufK + 8192;
        *(uint4*)(bufK + swz) = kreg;
        *(uint4*)(bufV + swz) = vreg;
        if (kb + 64 < NTOK) {
            kreg = kg[(kb + 64 + row)*4 + chk];
            vreg = vg[(kb + 64 + row)*4 + chk];
        }
        __syncthreads();

        // ---- S = Q K^T for 64 keys, then exp, pack P ----
        unsigned pb[16];
        #pragma unroll
        for (int j = 0; j < 8; j++) {
            unsigned b0, b1, b2, b3;
            {
                int r = j*8 + (lane & 7);
                int c = lane >> 3;
                unsigned a = smem_u32(bufK + r*128 + ((c ^ (r & 7))*16));
                ldmx4(b0, b1, b2, b3, a);
            }
            float c0 = 0.f, c1 = 0.f, c2 = 0.f, c3 = 0.f;
            mma16816(c0, c1, c2, c3, qf[0], qf[1], qf[2], qf[3], b0, b1);
            mma16816(c0, c1, c2, c3, qf[4], qf[5], qf[6], qf[7], b2, b3);
            float p0 = ex2f(fmaf(c0, L2E, nm));
            float p1 = ex2f(fmaf(c1, L2E, nm));
            float p2 = ex2f(fmaf(c2, L2E, nm));
            float p3 = ex2f(fmaf(c3, L2E, nm));
            l0 += p0 + p1;
            l1 += p2 + p3;
            pb[(j>>1)*4 + (j&1)*2 + 0] = cvt2(p1, p0);
            pb[(j>>1)*4 + (j&1)*2 + 1] = cvt2(p3, p2);
        }

        // ---- O += P V ----
        #pragma unroll
        for (int t = 0; t < 4; t++) {
            #pragma unroll
            for (int p = 0; p < 2; p++) {
                unsigned b0, b1, b2, b3;
                {
                    int key = t*16 + ((lane >> 3) & 1)*8 + (lane & 7);
                    int c   = p*2 + (lane >> 4);
                    unsigned a = smem_u32(bufV + key*128 + ((c ^ (key & 7))*16));
                    ldmx4t(b0, b1, b2, b3, a);
                }
                int nn = p*2;
                mma16816(o[nn*4+0], o[nn*4+1], o[nn*4+2], o[nn*4+3],
                         pb[t*4], pb[t*4+1], pb[t*4+2], pb[t*4+3], b0, b1);
                if (nn + 1 < 3)
                    mma16816(o[nn*4+4], o[nn*4+5], o[nn*4+6], o[nn*4+7],
                             pb[t*4], pb[t*4+1], pb[t*4+2], pb[t*4+3], b2, b3);
            }
        }
        it ^= 1;
    }

    // ---- finalize: reduce row-sums across quad, normalize, store ----
    l0 += __shfl_xor_sync(0xffffffffu, l0, 1);
    l0 += __shfl_xor_sync(0xffffffffu, l0, 2);
    l1 += __shfl_xor_sync(0xffffffffu, l1, 1);
    l1 += __shfl_xor_sync(0xffffffffu, l1, 2);
    float i0 = 1.f / l0, i1 = 1.f / l1;
    float* op = O + (size_t)(bh*NTOK + q0 + warp*16)*CHD;
    #pragma unroll
    for (int nn = 0; nn < 3; nn++) {
        int cc = nn*8 + t4*2;
        op[g*CHD + cc]         = o[nn*4+0]*i0;
        op[g*CHD + cc + 1]     = o[nn*4+1]*i0;
        op[(g+8)*CHD + cc]     = o[nn*4+2]*i1;
        op[(g+8)*CHD + cc + 1] = o[nn*4+3]*i1;
    }
}

// ---------------- proj 1x1 + residual, warp per pixel ----------------------
__global__ void __launch_bounds__(32*NWARPS)
proj_res_kernel(const float* __restrict__ x, const float* __restrict__ Ot,
                const float* __restrict__ pw, const float* __restrict__ pb,
                float* __restrict__ out)
{
    __shared__ float Wt[CC0*CC0];
    __shared__ float xs[NWARPS][CC0];
    for (int i = threadIdx.x; i < CC0*CC0; i += blockDim.x) {
        int o = i % CC0, c = i / CC0;
        Wt[i] = pw[o*CC0 + c];
    }
    __syncthreads();
    int warp = threadIdx.x >> 5, lane = threadIdx.x & 31;
    int pix  = blockIdx.x * NWARPS + warp;
    int b = pix / NTOK, n = pix % NTOK;
    if (lane < CHD) {
        xs[warp][lane]       = Ot[((size_t)(b*NHEADS + 0)*NTOK + n)*CHD + lane];
        xs[warp][CHD + lane] = Ot[((size_t)(b*NHEADS + 1)*NTOK + n)*CHD + lane];
    }
    __syncwarp();
    for (int o = lane; o < CC0; o += 32) {
        float acc = pb[o];
        #pragma unroll
        for (int c = 0; c < CC0; c++) acc += Wt[c*CC0 + o] * xs[warp][c];
        int gi = b*CC0*NTOK + o*NTOK + n;
        out[gi] = x[gi] + acc;
    }
}

// ---------------- gelu-gate + fo 1x1 + residual, warp per pixel ------------
__global__ void __launch_bounds__(32*NWARPS)
ffn_out_kernel(const float* __restrict__ x1, const float* __restrict__ y,
               const float* __restrict__ fow, const float* __restrict__ fob,
               float* __restrict__ out)
{
    __shared__ float Wt[HID*CC0];    // [j][o]
    __shared__ float gs[NWARPS][HID];
    for (int i = threadIdx.x; i < HID*CC0; i += blockDim.x) {
        int o = i % CC0, j = i / CC0;
        Wt[i] = fow[o*HID + j];
    }
    __syncthreads();
    int warp = threadIdx.x >> 5, lane = threadIdx.x & 31;
    int pix  = blockIdx.x * NWARPS + warp;
    int b = pix / NTOK, n = pix % NTOK;
    const float* yp = y + b*HID2*NTOK + n;
    #pragma unroll
    for (int j = lane; j < HID; j += 32) {
        float a  = yp[j*NTOK];
        float g2 = yp[(HID + j)*NTOK];
        float g  = 0.5f*a*(1.f + erff(a*0.70710678118654752f));   // exact gelu
        gs[warp][j] = g*g2;
    }
    __syncwarp();
    for (int o = lane; o < CC0; o += 32) {
        float acc = fob[o];
        #pragma unroll
        for (int j = 0; j < HID; j++) acc += Wt[j*CC0 + o] * gs[warp][j];
        int gi = b*CC0*NTOK + o*NTOK + n;
        out[gi] = x1[gi] + acc;
    }
}

// ---------------- launch ----------------------------------------------------
extern "C" void kernel_launch(void* const* d_in, const int* in_sizes, int n_in,
                              void* d_out, int out_size)
{
    const float* x    = (const float*)d_in[0];
    const float* n1w  = (const float*)d_in[1];
    const float* n1b  = (const float*)d_in[2];
    const float* qkvw = (const float*)d_in[3];
    const float* qkvb = (const float*)d_in[4];
    const float* qdww = (const float*)d_in[5];
    const float* qdwb = (const float*)d_in[6];
    const float* temp = (const float*)d_in[7];
    const float* pw   = (const float*)d_in[8];
    const float* pb   = (const float*)d_in[9];
    const float* n2w  = (const float*)d_in[10];
    const float* n2b  = (const float*)d_in[11];
    const float* fiw  = (const float*)d_in[12];
    const float* fib  = (const float*)d_in[13];
    const float* fdww = (const float*)d_in[14];
    const float* fdwb = (const float*)d_in[15];
    const float* fow  = (const float*)d_in[16];
    const float* fob  = (const float*)d_in[17];
    float* out = (float*)d_out;

    float *qkv1, *qkv2, *Op, *x1, *ff1, *ff2;
    __nv_bfloat16 *Qp, *Kp, *Vp;
    cudaGetSymbolAddress((void**)&qkv1, g_qkv1);
    cudaGetSymbolAddress((void**)&qkv2, g_qkv2);
    cudaGetSymbolAddress((void**)&Qp,   g_qb);
    cudaGetSymbolAddress((void**)&Kp,   g_kb);
    cudaGetSymbolAddress((void**)&Vp,   g_vb);
    cudaGetSymbolAddress((void**)&Op,   g_o);
    cudaGetSymbolAddress((void**)&x1,   g_x1);
    cudaGetSymbolAddress((void**)&ff1,  g_ff1);
    cudaGetSymbolAddress((void**)&ff2,  g_ff2);

    const int pixblocks = (BB*NTOK) / NWARPS;   // 1024

    ln_conv1x1_kernel<CC0, C3><<<pixblocks, 32*NWARPS>>>(x, n1w, n1b, qkvw, qkvb, qkv1);
    dwconv3_kernel<C3><<<(BB*C3*NTOK + 255)/256, 256>>>(qkv1, qdww, qdwb, qkv2);
    qkv_norm_bf16_kernel<<<(BB*NHEADS*NTOK + 255)/256, 256>>>(qkv2, temp, Qp, Kp, Vp);

    dim3 ag(NTOK/128, BB*NHEADS);                // (32, 4)
    attn_mma_kernel<<<ag, 256>>>(Qp, Kp, Vp, temp, Op);

    proj_res_kernel<<<pixblocks, 32*NWARPS>>>(x, Op, pw, pb, x1);
    ln_conv1x1_kernel<CC0, HID2><<<pixblocks, 32*NWARPS>>>(x1, n2w, n2b, fiw, fib, ff1);
    dwconv3_kernel<HID2><<<(BB*HID2*NTOK + 255)/256, 256>>>(ff1, fdww, fdwb, ff2);
    ffn_out_kernel<<<pixblocks, 32*NWARPS>>>(x1, ff2, fow, fob, out);
}

// round 3
// speedup vs baseline: 3.5917x; 1.7297x over previous
#include <cuda_runtime.h>
#include <cuda_bf16.h>
#include <math.h>

// ---------------- problem constants ----------------
#define BB      2
#define CC0     48          // dim
#define NHEADS  2
#define CHD     24          // channels per head
#define DP      32          // padded head dim (bf16 tensors)
#define NTOK    4096        // 64*64
#define NPIX    (BB*NTOK)   // 8192
#define C3      144         // dim*3
#define HID     96
#define HID2    192
#define NSPL    4           // attention KV splits

// ---------------- scratch (device globals; no allocation allowed) ----------
__device__ float g_qkv1[BB*C3*NTOK];
__device__ float g_qkv2[BB*C3*NTOK];
__device__ __nv_bfloat16 g_qb[BB*NHEADS*NTOK*DP];
__device__ __nv_bfloat16 g_kb[BB*NHEADS*NTOK*DP];
__device__ __nv_bfloat16 g_vb[BB*NHEADS*NTOK*DP];
__device__ float g_part[BB*NHEADS*NTOK*NSPL*25];   // unnormalized O + l
__device__ float g_o [BB*CC0*NTOK];                // merged attn out, channel-major
__device__ float g_x1[BB*CC0*NTOK];
__device__ float g_ff1[BB*HID2*NTOK];
__device__ float g_ff3[BB*HID*NTOK];               // gated hidden

// ---------------- small asm helpers ----------------------------------------
__device__ __forceinline__ unsigned smem_u32(const void* p) {
    return (unsigned)__cvta_generic_to_shared(p);
}
__device__ __forceinline__ void ldmx4(unsigned& r0, unsigned& r1, unsigned& r2,
                                      unsigned& r3, unsigned a) {
    asm volatile("ldmatrix.sync.aligned.m8n8.x4.shared.b16 {%0,%1,%2,%3}, [%4];"
                 : "=r"(r0), "=r"(r1), "=r"(r2), "=r"(r3) : "r"(a));
}
__device__ __forceinline__ void ldmx4t(unsigned& r0, unsigned& r1, unsigned& r2,
                                       unsigned& r3, unsigned a) {
    asm volatile("ldmatrix.sync.aligned.m8n8.x4.trans.shared.b16 {%0,%1,%2,%3}, [%4];"
                 : "=r"(r0), "=r"(r1), "=r"(r2), "=r"(r3) : "r"(a));
}
__device__ __forceinline__ void mma16816(float& d0, float& d1, float& d2, float& d3,
                                         unsigned a0, unsigned a1, unsigned a2, unsigned a3,
                                         unsigned b0, unsigned b1) {
    asm volatile("mma.sync.aligned.m16n8k16.row.col.f32.bf16.bf16.f32 "
                 "{%0,%1,%2,%3},{%4,%5,%6,%7},{%8,%9},{%0,%1,%2,%3};"
                 : "+f"(d0), "+f"(d1), "+f"(d2), "+f"(d3)
                 : "r"(a0), "r"(a1), "r"(a2), "r"(a3), "r"(b0), "r"(b1));
}
__device__ __forceinline__ unsigned cvt2(float hi, float lo) {
    unsigned r;
    asm("cvt.rn.bf16x2.f32 %0, %1, %2;" : "=r"(r) : "f"(hi), "f"(lo));
    return r;
}
__device__ __forceinline__ float ex2f(float x) {
    float y; asm("ex2.approx.ftz.f32 %0, %1;" : "=f"(y) : "f"(x)); return y;
}

// ---------------- 1x1 conv (optionally LN in, residual out), z-sliced ------
// thread = pixel; each thread computes OPT consecutive output channels.
// grid.x = NPIX/256, grid.y = COUT/OPT.
template<int CIN, int COUT, int OPT, bool LN>
__global__ void __launch_bounds__(256)
conv1x1_z(const float* __restrict__ in,
          const float* __restrict__ lnw, const float* __restrict__ lnb,
          const float* __restrict__ w,   const float* __restrict__ bias,
          const float* __restrict__ res, float* __restrict__ out)
{
    __shared__ float ws[CIN*OPT];      // [c][oo]
    const int o0 = blockIdx.y * OPT;
    for (int i = threadIdx.x; i < CIN*OPT; i += 256) {
        int oo = i % OPT, c = i / OPT;
        ws[i] = w[(o0 + oo)*CIN + c];
    }
    __syncthreads();

    int pix = blockIdx.x*256 + threadIdx.x;
    int b = pix >> 12, n = pix & (NTOK-1);
    const float* ip = in + (size_t)b*CIN*NTOK + n;

    float acc[OPT];
    #pragma unroll
    for (int oo = 0; oo < OPT; oo++) acc[oo] = bias[o0 + oo];

    if (LN) {
        float v[CIN];
        float s = 0.f, ss = 0.f;
        #pragma unroll
        for (int c = 0; c < CIN; c++) {
            float u = ip[c*NTOK];
            v[c] = u; s += u; ss += u*u;
        }
        float mu  = s * (1.f/CIN);
        float var = ss * (1.f/CIN) - mu*mu;
        float inv = rsqrtf(var + 1e-5f);
        #pragma unroll
        for (int c = 0; c < CIN; c++) {
            float xc = (v[c] - mu)*inv*__ldg(lnw + c) + __ldg(lnb + c);
            #pragma unroll
            for (int oo = 0; oo < OPT; oo++)
                acc[oo] = fmaf(xc, ws[c*OPT + oo], acc[oo]);
        }
    } else {
        #pragma unroll 4
        for (int c = 0; c < CIN; c++) {
            float xc = ip[c*NTOK];
            #pragma unroll
            for (int oo = 0; oo < OPT; oo++)
                acc[oo] = fmaf(xc, ws[c*OPT + oo], acc[oo]);
        }
    }

    float* op = out + (size_t)(b*COUT + o0)*NTOK + n;
    if (res) {
        const float* rp = res + (size_t)(b*COUT + o0)*NTOK + n;
        #pragma unroll
        for (int oo = 0; oo < OPT; oo++) op[oo*NTOK] = acc[oo] + rp[oo*NTOK];
    } else {
        #pragma unroll
        for (int oo = 0; oo < OPT; oo++) op[oo*NTOK] = acc[oo];
    }
}

// ---------------- depthwise 3x3, SAME (zero pad) ---------------------------
template<int CCH>
__global__ void dwconv3_kernel(const float* __restrict__ in, const float* __restrict__ w,
                               const float* __restrict__ bias, float* __restrict__ out)
{
    int idx = blockIdx.x*blockDim.x + threadIdx.x;   // over BB*CCH*NTOK
    if (idx >= BB*CCH*NTOK) return;
    int p  = idx & (NTOK-1);
    int bc = idx >> 12;
    int c  = bc % CCH;
    int x0 = p & 63, y0 = p >> 6;
    const float* ip = in + bc*NTOK;
    const float* wp = w + c*9;
    float acc = bias[c];
    #pragma unroll
    for (int ky = 0; ky < 3; ky++) {
        int y = y0 + ky - 1;
        if ((unsigned)y < 64u) {
            #pragma unroll
            for (int kx = 0; kx < 3; kx++) {
                int xx = x0 + kx - 1;
                if ((unsigned)xx < 64u) acc += wp[ky*3 + kx] * ip[y*64 + xx];
            }
        }
    }
    out[idx] = acc;
}

// ---------------- FFN depthwise 3x3 + gelu gate fused ----------------------
// thread = (b, j<HID, pixel): computes dwconv for channels j and j+HID,
// gates: out = gelu(a) * g2   (exact gelu)
__global__ void dwconv_gate_kernel(const float* __restrict__ in, const float* __restrict__ w,
                                   const float* __restrict__ bias, float* __restrict__ out)
{
    int idx = blockIdx.x*blockDim.x + threadIdx.x;   // over BB*HID*NTOK
    if (idx >= BB*HID*NTOK) return;
    int p  = idx & (NTOK-1);
    int bj = idx >> 12;
    int j  = bj % HID;
    int b  = bj / HID;
    int x0 = p & 63, y0 = p >> 6;
    const float* ip1 = in + ((size_t)b*HID2 + j)*NTOK;
    const float* ip2 = in + ((size_t)b*HID2 + HID + j)*NTOK;
    const float* w1 = w + j*9;
    const float* w2 = w + (HID + j)*9;
    float a  = bias[j];
    float g2 = bias[HID + j];
    #pragma unroll
    for (int ky = 0; ky < 3; ky++) {
        int y = y0 + ky - 1;
        if ((unsigned)y < 64u) {
            #pragma unroll
            for (int kx = 0; kx < 3; kx++) {
                int xx = x0 + kx - 1;
                if ((unsigned)xx < 64u) {
                    a  += w1[ky*3 + kx] * ip1[y*64 + xx];
                    g2 += w2[ky*3 + kx] * ip2[y*64 + xx];
                }
            }
        }
    }
    float g = 0.5f*a*(1.f + erff(a*0.70710678118654752f));
    out[((size_t)b*HID + j)*NTOK + p] = g*g2;
}

// ---------------- split q/k/v, l2-normalize, fold temp, emit bf16 ----------
__global__ void qkv_norm_bf16_kernel(const float* __restrict__ qkv,
                                     const float* __restrict__ temp,
                                     __nv_bfloat16* __restrict__ Q,
                                     __nv_bfloat16* __restrict__ K,
                                     __nv_bfloat16* __restrict__ V)
{
    int idx = blockIdx.x*blockDim.x + threadIdx.x;   // over BB*NHEADS*NTOK
    if (idx >= BB*NHEADS*NTOK) return;
    int n  = idx & (NTOK-1);
    int bh = idx >> 12;
    int b = bh >> 1, hd = bh & 1;
    const float* base = qkv + b*C3*NTOK + n;
    float t = temp[hd];
    float buf[CHD];
    unsigned tmp[DP/2];
    #pragma unroll
    for (int i = CHD/2; i < DP/2; i++) tmp[i] = 0u;

    float ss = 0.f;
    #pragma unroll
    for (int c = 0; c < CHD; c++) { float u = base[(hd*CHD + c)*NTOK]; buf[c] = u; ss += u*u; }
    float inv = t / fmaxf(sqrtf(ss), 1e-12f);
    #pragma unroll
    for (int i = 0; i < CHD/2; i++) tmp[i] = cvt2(buf[2*i+1]*inv, buf[2*i]*inv);
    {
        uint4* p4 = (uint4*)(Q + (size_t)idx*DP);
        p4[0] = make_uint4(tmp[0], tmp[1], tmp[2],  tmp[3]);
        p4[1] = make_uint4(tmp[4], tmp[5], tmp[6],  tmp[7]);
        p4[2] = make_uint4(tmp[8], tmp[9], tmp[10], tmp[11]);
        p4[3] = make_uint4(tmp[12],tmp[13],tmp[14], tmp[15]);
    }
    ss = 0.f;
    #pragma unroll
    for (int c = 0; c < CHD; c++) { float u = base[(CC0 + hd*CHD + c)*NTOK]; buf[c] = u; ss += u*u; }
    inv = 1.f / fmaxf(sqrtf(ss), 1e-12f);
    #pragma unroll
    for (int i = 0; i < CHD/2; i++) tmp[i] = cvt2(buf[2*i+1]*inv, buf[2*i]*inv);
    {
        uint4* p4 = (uint4*)(K + (size_t)idx*DP);
        p4[0] = make_uint4(tmp[0], tmp[1], tmp[2],  tmp[3]);
        p4[1] = make_uint4(tmp[4], tmp[5], tmp[6],  tmp[7]);
        p4[2] = make_uint4(tmp[8], tmp[9], tmp[10], tmp[11]);
        p4[3] = make_uint4(tmp[12],tmp[13],tmp[14], tmp[15]);
    }
    #pragma unroll
    for (int i = 0; i < CHD/2; i++) {
        float u0 = base[(2*CC0 + hd*CHD + 2*i)*NTOK];
        float u1 = base[(2*CC0 + hd*CHD + 2*i + 1)*NTOK];
        tmp[i] = cvt2(u1, u0);
    }
    {
        uint4* p4 = (uint4*)(V + (size_t)idx*DP);
        p4[0] = make_uint4(tmp[0], tmp[1], tmp[2],  tmp[3]);
        p4[1] = make_uint4(tmp[4], tmp[5], tmp[6],  tmp[7]);
        p4[2] = make_uint4(tmp[8], tmp[9], tmp[10], tmp[11]);
        p4[3] = make_uint4(tmp[12],tmp[13],tmp[14], tmp[15]);
    }
}

// ---------------- bf16 mma.sync flash attention, split-KV -------------------
// grid (32 q-tiles, 4 bh, NSPL splits), 256 threads = 8 warps.
// Fixed softmax shift m = |temp| ==> split partials merge by plain sum.
#define KVSEG (NTOK/NSPL)   // 1024

__global__ void __launch_bounds__(256)
attn_mma_kernel(const __nv_bfloat16* __restrict__ Qb,
                const __nv_bfloat16* __restrict__ Kb,
                const __nv_bfloat16* __restrict__ Vb,
                const float* __restrict__ temp,
                float* __restrict__ part)
{
    __shared__ __align__(16) unsigned char smem_raw[2*16384];

    int tid  = threadIdx.x;
    int warp = tid >> 5, lane = tid & 31;
    int g    = lane >> 2;
    int t4   = lane & 3;
    int bh   = blockIdx.y;
    int q0   = blockIdx.x * 128;
    int spl  = blockIdx.z;
    int kv0  = spl * KVSEG;

    const float L2E = 1.4426950408889634f;
    float m  = fabsf(temp[bh & 1]);
    float nm = -m * L2E;

    unsigned qf[8];
    {
        const unsigned* q32 = (const unsigned*)(Qb + (size_t)(bh*NTOK + q0 + warp*16)*DP);
        #pragma unroll
        for (int kt = 0; kt < 2; kt++) {
            qf[kt*4+0] = q32[g*16       + kt*8 + t4];
            qf[kt*4+1] = q32[(g+8)*16   + kt*8 + t4];
            qf[kt*4+2] = q32[g*16       + kt*8 + 4 + t4];
            qf[kt*4+3] = q32[(g+8)*16   + kt*8 + 4 + t4];
        }
    }

    float o[12];
    #pragma unroll
    for (int i = 0; i < 12; i++) o[i] = 0.f;
    float l0 = 0.f, l1 = 0.f;

    const uint4* kg = (const uint4*)(Kb + (size_t)bh*NTOK*DP);
    const uint4* vg = (const uint4*)(Vb + (size_t)bh*NTOK*DP);
    int row = tid >> 2, chk = tid & 3;
    unsigned swz = row*128 + ((chk ^ (row & 7))*16);

    uint4 kreg = kg[(kv0 + row)*4 + chk];
    uint4 vreg = vg[(kv0 + row)*4 + chk];
    int it = 0;

    for (int kb = kv0; kb < kv0 + KVSEG; kb += 64) {
        unsigned char* bufK = smem_raw + it*16384;
        unsigned char* bufV = bufK + 8192;
        *(uint4*)(bufK + swz) = kreg;
        *(uint4*)(bufV + swz) = vreg;
        if (kb + 64 < kv0 + KVSEG) {
            kreg = kg[(kb + 64 + row)*4 + chk];
            vreg = vg[(kb + 64 + row)*4 + chk];
        }
        __syncthreads();

        unsigned pb[16];
        #pragma unroll
        for (int j = 0; j < 8; j++) {
            unsigned b0, b1, b2, b3;
            {
                int r = j*8 + (lane & 7);
                int c = lane >> 3;
                unsigned a = smem_u32(bufK + r*128 + ((c ^ (r & 7))*16));
                ldmx4(b0, b1, b2, b3, a);
            }
            float c0 = 0.f, c1 = 0.f, c2 = 0.f, c3 = 0.f;
            mma16816(c0, c1, c2, c3, qf[0], qf[1], qf[2], qf[3], b0, b1);
            mma16816(c0, c1, c2, c3, qf[4], qf[5], qf[6], qf[7], b2, b3);
            float p0 = ex2f(fmaf(c0, L2E, nm));
            float p1 = ex2f(fmaf(c1, L2E, nm));
            float p2 = ex2f(fmaf(c2, L2E, nm));
            float p3 = ex2f(fmaf(c3, L2E, nm));
            l0 += p0 + p1;
            l1 += p2 + p3;
            pb[(j>>1)*4 + (j&1)*2 + 0] = cvt2(p1, p0);
            pb[(j>>1)*4 + (j&1)*2 + 1] = cvt2(p3, p2);
        }

        #pragma unroll
        for (int t = 0; t < 4; t++) {
            #pragma unroll
            for (int p = 0; p < 2; p++) {
                unsigned b0, b1, b2, b3;
                {
                    int key = t*16 + ((lane >> 3) & 1)*8 + (lane & 7);
                    int c   = p*2 + (lane >> 4);
                    unsigned a = smem_u32(bufV + key*128 + ((c ^ (key & 7))*16));
                    ldmx4t(b0, b1, b2, b3, a);
                }
                int nn = p*2;
                mma16816(o[nn*4+0], o[nn*4+1], o[nn*4+2], o[nn*4+3],
                         pb[t*4], pb[t*4+1], pb[t*4+2], pb[t*4+3], b0, b1);
                if (nn + 1 < 3)
                    mma16816(o[nn*4+4], o[nn*4+5], o[nn*4+6], o[nn*4+7],
                             pb[t*4], pb[t*4+1], pb[t*4+2], pb[t*4+3], b2, b3);
            }
        }
        it ^= 1;
        __syncthreads();
    }

    // reduce row-sums across quad, write unnormalized partials
    l0 += __shfl_xor_sync(0xffffffffu, l0, 1);
    l0 += __shfl_xor_sync(0xffffffffu, l0, 2);
    l1 += __shfl_xor_sync(0xffffffffu, l1, 1);
    l1 += __shfl_xor_sync(0xffffffffu, l1, 2);
    size_t r0 = (size_t)(bh*NTOK + q0 + warp*16 + g);
    float* p0 = part + (r0*NSPL + spl)*25;
    float* p1 = part + ((r0 + 8)*NSPL + spl)*25;
    #pragma unroll
    for (int nn = 0; nn < 3; nn++) {
        int cc = nn*8 + t4*2;
        p0[cc]     = o[nn*4+0];
        p0[cc + 1] = o[nn*4+1];
        p1[cc]     = o[nn*4+2];
        p1[cc + 1] = o[nn*4+3];
    }
    if (t4 == 0) { p0[24] = l0; p1[24] = l1; }
}

// ---------------- merge split-KV partials -> channel-major O ---------------
__global__ void attn_merge_kernel(const float* __restrict__ part, float* __restrict__ O)
{
    int idx = blockIdx.x*blockDim.x + threadIdx.x;   // over BB*NHEADS*NTOK
    if (idx >= BB*NHEADS*NTOK) return;
    int n  = idx & (NTOK-1);
    int bh = idx >> 12;
    int b = bh >> 1, hd = bh & 1;
    const float* pp = part + (size_t)idx*NSPL*25;
    float oo[CHD];
    #pragma unroll
    for (int c = 0; c < CHD; c++) oo[c] = 0.f;
    float L = 0.f;
    #pragma unroll
    for (int sp = 0; sp < NSPL; sp++) {
        const float* q = pp + sp*25;
        #pragma unroll
        for (int c = 0; c < CHD; c++) oo[c] += q[c];
        L += q[24];
    }
    float invL = 1.f / L;
    float* op = O + ((size_t)b*CC0 + hd*CHD)*NTOK + n;
    #pragma unroll
    for (int c = 0; c < CHD; c++) op[c*NTOK] = oo[c]*invL;
}

// ---------------- launch ----------------------------------------------------
extern "C" void kernel_launch(void* const* d_in, const int* in_sizes, int n_in,
                              void* d_out, int out_size)
{
    const float* x    = (const float*)d_in[0];
    const float* n1w  = (const float*)d_in[1];
    const float* n1b  = (const float*)d_in[2];
    const float* qkvw = (const float*)d_in[3];
    const float* qkvb = (const float*)d_in[4];
    const float* qdww = (const float*)d_in[5];
    const float* qdwb = (const float*)d_in[6];
    const float* temp = (const float*)d_in[7];
    const float* pw   = (const float*)d_in[8];
    const float* pb   = (const float*)d_in[9];
    const float* n2w  = (const float*)d_in[10];
    const float* n2b  = (const float*)d_in[11];
    const float* fiw  = (const float*)d_in[12];
    const float* fib  = (const float*)d_in[13];
    const float* fdww = (const float*)d_in[14];
    const float* fdwb = (const float*)d_in[15];
    const float* fow  = (const float*)d_in[16];
    const float* fob  = (const float*)d_in[17];
    float* out = (float*)d_out;

    float *qkv1, *qkv2, *partp, *Oc, *x1, *ff1, *ff3;
    __nv_bfloat16 *Qp, *Kp, *Vp;
    cudaGetSymbolAddress((void**)&qkv1,  g_qkv1);
    cudaGetSymbolAddress((void**)&qkv2,  g_qkv2);
    cudaGetSymbolAddress((void**)&Qp,    g_qb);
    cudaGetSymbolAddress((void**)&Kp,    g_kb);
    cudaGetSymbolAddress((void**)&Vp,    g_vb);
    cudaGetSymbolAddress((void**)&partp, g_part);
    cudaGetSymbolAddress((void**)&Oc,    g_o);
    cudaGetSymbolAddress((void**)&x1,    g_x1);
    cudaGetSymbolAddress((void**)&ff1,   g_ff1);
    cudaGetSymbolAddress((void**)&ff3,   g_ff3);

    // 1. LN1 + qkv 1x1 : x -> g_qkv1 [b][144][pix]
    conv1x1_z<CC0, C3, 24, true><<<dim3(NPIX/256, C3/24), 256>>>(
        x, n1w, n1b, qkvw, qkvb, nullptr, qkv1);
    // 2. depthwise 3x3 on 144 channels
    dwconv3_kernel<C3><<<(BB*C3*NTOK + 255)/256, 256>>>(qkv1, qdww, qdwb, qkv2);
    // 3. split/l2norm/bf16
    qkv_norm_bf16_kernel<<<(BB*NHEADS*NTOK + 255)/256, 256>>>(qkv2, temp, Qp, Kp, Vp);
    // 4. flash attention, split-KV
    dim3 ag(NTOK/128, BB*NHEADS, NSPL);
    attn_mma_kernel<<<ag, 256>>>(Qp, Kp, Vp, temp, partp);
    // 5. merge partials -> g_o [b][48][pix]
    attn_merge_kernel<<<(BB*NHEADS*NTOK + 255)/256, 256>>>(partp, Oc);
    // 6. proj 1x1 + residual -> g_x1
    conv1x1_z<CC0, CC0, 24, false><<<dim3(NPIX/256, CC0/24), 256>>>(
        Oc, nullptr, nullptr, pw, pb, x, x1);
    // 7. LN2 + fi 1x1 -> g_ff1 [b][192][pix]
    conv1x1_z<CC0, HID2, 24, true><<<dim3(NPIX/256, HID2/24), 256>>>(
        x1, n2w, n2b, fiw, fib, nullptr, ff1);
    // 8. FFN depthwise + gelu gate -> g_ff3 [b][96][pix]
    dwconv_gate_kernel<<<(BB*HID*NTOK + 255)/256, 256>>>(ff1, fdww, fdwb, ff3);
    // 9. fo 1x1 + residual -> out
    conv1x1_z<HID, CC0, 24, false><<<dim3(NPIX/256, CC0/24), 256>>>(
        ff3, nullptr, nullptr, fow, fob, x1, out);
}